// round 14
// baseline (speedup 1.0000x reference)
#include <cuda_runtime.h>
#include <math.h>

#define BB 4
#define NN 2048
#define FD 128
#define MROWS (BB*NN)     // 8192 rows
#define KTOT (NN+1)
#define NCH 128
#define CLEN 16
#define NBLK 128
#define NTHR 256

// ---------------- scratch (device globals; no allocation) ----------------
__device__ float g_h1[MROWS*FD];
__device__ float g_h2[MROWS*FD];
__device__ float g_g [MROWS*FD];
__device__ float g_s[MROWS];
__device__ float g_d[MROWS];
__device__ float g_sortedD[MROWS];
__device__ int   g_perm[MROWS];
__device__ float g_sufE1[BB*KTOT];
__device__ float g_preH [BB*KTOT*FD];
__device__ float g_sufEH[BB*KTOT*FD];
__device__ float g_tot[BB*2*NCH*FD];
__device__ float g_off[BB*2*(NCH+1)*FD];
__device__ int   g_rk[MROWS];
__device__ float g_rE[MROWS];
__device__ float g_rw[MROWS];
__device__ float g_rinv[MROWS];

// ---------------- software grid barrier ----------------
__device__ unsigned g_bar_cnt;
__device__ volatile unsigned g_bar_gen;

__device__ __forceinline__ void grid_bar() {
    __threadfence();          // each thread's prior global writes -> L2
    __syncthreads();          // all fences done before arrival
    if (threadIdx.x == 0) {
        unsigned gen = g_bar_gen;
        if (atomicAdd(&g_bar_cnt, 1u) == NBLK - 1u) {
            g_bar_cnt = 0u;
            __threadfence();
            g_bar_gen = gen + 1u;
        } else {
            while (g_bar_gen == gen) __nanosleep(32);
        }
    }
    __syncthreads();
}

// ---------------- tf32 helpers ----------------
__device__ __forceinline__ float tf32_rn(float x) {
    unsigned u;
    asm("cvt.rna.tf32.f32 %0, %1;" : "=r"(u) : "f"(x));
    return __uint_as_float(u);
}

__device__ __forceinline__ void mma8(float* d, const float* a, float b0, float b1) {
    asm volatile(
        "mma.sync.aligned.m16n8k8.row.col.f32.tf32.tf32.f32 "
        "{%0,%1,%2,%3},{%4,%5,%6,%7},{%8,%9},{%0,%1,%2,%3};"
        : "+f"(d[0]), "+f"(d[1]), "+f"(d[2]), "+f"(d[3])
        : "r"(__float_as_uint(a[0])), "r"(__float_as_uint(a[1])),
          "r"(__float_as_uint(a[2])), "r"(__float_as_uint(a[3])),
          "r"(__float_as_uint(b0)),  "r"(__float_as_uint(b1)));
}

// ================= persistent mega-kernel: whole GAT in one launch =========
__global__ __launch_bounds__(NTHR, 1) void gat_mega(
    const float* __restrict__ x,
    const float* __restrict__ W1,   const float* __restrict__ b1,
    const float* __restrict__ asrcA, const float* __restrict__ adstA,
    const float* __restrict__ abA,
    const float* __restrict__ gamma, const float* __restrict__ beta,
    const float* __restrict__ mean,  const float* __restrict__ var,
    float* __restrict__ out)
{
    __shared__ __align__(16) float SM[9216];   // 36 KB, reused per phase
    float (*Ah)[17] = (float(*)[17])(SM);
    float (*Al)[17] = (float(*)[17])(SM + 2176);
    float (*Bh)[17] = (float(*)[17])(SM + 4352);
    float (*Bl)[17] = (float(*)[17])(SM + 6528);
    float (*sh_s)[128] = (float(*)[128])(SM + 8704);
    float (*sh_d)[128] = (float(*)[128])(SM + 8960);

    const int blk = blockIdx.x;
    const int tid = threadIdx.x;

    for (int stage = 0; stage < 2; stage++) {
        const int klay = stage * 2;
        const float* W    = W1 + klay*FD*FD;     // two layers contiguous (256 rows)
        const float* bias = b1 + klay*FD;
        const float* asrc = asrcA + klay*FD;
        const float* adst = adstA + klay*FD;

        // ============ PHASE 1: fused GEMM (3xTF32) + s/d epilogue ============
        {
            int wid = tid >> 5, lane = tid & 31;
            int gid = lane >> 2, tig = lane & 3;
            int warp_m = wid & 3, warp_n = wid >> 2;
            int row0 = (blk & 63) * 128;
            int coly = blk >> 6;              // 0 -> h1, 1 -> h2
            int col0 = coly * 128;

            float acc[2][8][4];
            #pragma unroll
            for (int mt = 0; mt < 2; mt++)
                #pragma unroll
                for (int nt = 0; nt < 8; nt++)
                    #pragma unroll
                    for (int q = 0; q < 4; q++) acc[mt][nt][q] = 0.f;

            int lrow = tid >> 2;              // 0..63
            int lq   = (tid & 3) * 4;

            for (int kt = 0; kt < FD; kt += 16) {
                float4 xa, xb;
                if (stage == 0) {
                    xa = *(const float4*)(x + (row0+lrow   )*FD + kt + lq);
                    xb = *(const float4*)(x + (row0+lrow+64)*FD + kt + lq);
                } else {
                    xa = __ldcg((const float4*)(g_g + (row0+lrow   )*FD + kt + lq));
                    xb = __ldcg((const float4*)(g_g + (row0+lrow+64)*FD + kt + lq));
                }
                float4 wa = *(const float4*)(W + (col0+lrow   )*FD + kt + lq);
                float4 wb = *(const float4*)(W + (col0+lrow+64)*FD + kt + lq);
                __syncthreads();
                {
                    float v[4] = {xa.x, xa.y, xa.z, xa.w};
                    #pragma unroll
                    for (int c = 0; c < 4; c++) {
                        float h = tf32_rn(v[c]);
                        Ah[lrow][lq+c] = h; Al[lrow][lq+c] = tf32_rn(v[c] - h);
                    }
                }
                {
                    float v[4] = {xb.x, xb.y, xb.z, xb.w};
                    #pragma unroll
                    for (int c = 0; c < 4; c++) {
                        float h = tf32_rn(v[c]);
                        Ah[lrow+64][lq+c] = h; Al[lrow+64][lq+c] = tf32_rn(v[c] - h);
                    }
                }
                {
                    float v[4] = {wa.x, wa.y, wa.z, wa.w};
                    #pragma unroll
                    for (int c = 0; c < 4; c++) {
                        float h = tf32_rn(v[c]);
                        Bh[lrow][lq+c] = h; Bl[lrow][lq+c] = tf32_rn(v[c] - h);
                    }
                }
                {
                    float v[4] = {wb.x, wb.y, wb.z, wb.w};
                    #pragma unroll
                    for (int c = 0; c < 4; c++) {
                        float h = tf32_rn(v[c]);
                        Bh[lrow+64][lq+c] = h; Bl[lrow+64][lq+c] = tf32_rn(v[c] - h);
                    }
                }
                __syncthreads();

                #pragma unroll
                for (int kk = 0; kk < 16; kk += 8) {
                    float a_h[2][4], a_l[2][4];
                    #pragma unroll
                    for (int mt = 0; mt < 2; mt++) {
                        int r = warp_m*32 + mt*16;
                        a_h[mt][0] = Ah[r+gid  ][kk+tig];   a_h[mt][1] = Ah[r+gid+8][kk+tig];
                        a_h[mt][2] = Ah[r+gid  ][kk+tig+4]; a_h[mt][3] = Ah[r+gid+8][kk+tig+4];
                        a_l[mt][0] = Al[r+gid  ][kk+tig];   a_l[mt][1] = Al[r+gid+8][kk+tig];
                        a_l[mt][2] = Al[r+gid  ][kk+tig+4]; a_l[mt][3] = Al[r+gid+8][kk+tig+4];
                    }
                    #pragma unroll
                    for (int nt = 0; nt < 8; nt++) {
                        int cc = warp_n*64 + nt*8 + gid;
                        float bh0 = Bh[cc][kk+tig], bh1 = Bh[cc][kk+tig+4];
                        float bl0 = Bl[cc][kk+tig], bl1 = Bl[cc][kk+tig+4];
                        #pragma unroll
                        for (int mt = 0; mt < 2; mt++) {
                            mma8(acc[mt][nt], a_h[mt], bh0, bh1);
                            mma8(acc[mt][nt], a_l[mt], bh0, bh1);
                            mma8(acc[mt][nt], a_h[mt], bl0, bl1);
                        }
                    }
                }
            }

            float* D = coly ? g_h2 : g_h1;
            float ps[2][2] = {{0.f,0.f},{0.f,0.f}};
            float pd[2][2] = {{0.f,0.f},{0.f,0.f}};
            #pragma unroll
            for (int mt = 0; mt < 2; mt++) {
                #pragma unroll
                for (int nt = 0; nt < 8; nt++) {
                    int col = warp_n*64 + nt*8 + tig*2;
                    float bv0 = bias[col0 + col];
                    float bv1 = bias[col0 + col + 1];
                    float v00 = acc[mt][nt][0]+bv0, v01 = acc[mt][nt][1]+bv1;
                    float v10 = acc[mt][nt][2]+bv0, v11 = acc[mt][nt][3]+bv1;
                    int r0 = row0 + warp_m*32 + mt*16 + gid;
                    *(float2*)(D + r0*FD + col)     = make_float2(v00, v01);
                    *(float2*)(D + (r0+8)*FD + col) = make_float2(v10, v11);
                    if (coly == 0) {
                        float a0 = asrc[col], a1 = asrc[col+1];
                        float d0 = adst[col], d1 = adst[col+1];
                        ps[mt][0] += v00*a0 + v01*a1;  pd[mt][0] += v00*d0 + v01*d1;
                        ps[mt][1] += v10*a0 + v11*a1;  pd[mt][1] += v10*d0 + v11*d1;
                    }
                }
            }
            if (coly == 0) {
                #pragma unroll
                for (int mt = 0; mt < 2; mt++)
                    #pragma unroll
                    for (int sel = 0; sel < 2; sel++) {
                        float sv = ps[mt][sel], dv = pd[mt][sel];
                        sv += __shfl_xor_sync(0xffffffffu, sv, 1);
                        sv += __shfl_xor_sync(0xffffffffu, sv, 2);
                        dv += __shfl_xor_sync(0xffffffffu, dv, 1);
                        dv += __shfl_xor_sync(0xffffffffu, dv, 2);
                        if (tig == 0) {
                            int lrw = warp_m*32 + mt*16 + sel*8 + gid;
                            sh_s[warp_n][lrw] = sv;
                            sh_d[warp_n][lrw] = dv;
                        }
                    }
                __syncthreads();
                if (tid < 128) {
                    g_s[row0 + tid] = sh_s[0][tid] + sh_s[1][tid];
                    g_d[row0 + tid] = sh_d[0][tid] + sh_d[1][tid];
                }
            }
        }
        grid_bar();

        // ============ PHASE 2: brute-force exact rank (sort replacement) =====
        {
            float* sd = SM;                       // 2048 floats
            int b = blk >> 5;
            int chunk = blk & 31;
            for (int j = tid; j < NN; j += NTHR)
                sd[j] = __ldcg(&g_d[b*NN + j]);
            __syncthreads();
            int i = chunk*64 + (tid >> 2);
            int q = tid & 3;
            float di = sd[i];
            int cnt = 0;
            int base = q * 512;
            #pragma unroll 8
            for (int t = 0; t < 512; t++) {
                int j = base + ((t + q*13) & 511);
                float dj = sd[j];
                cnt += (dj < di) || (dj == di && j < i);
            }
            cnt += __shfl_xor_sync(0xffffffffu, cnt, 1);
            cnt += __shfl_xor_sync(0xffffffffu, cnt, 2);
            if (q == 0) {
                g_perm[b*NN + cnt] = i;
                g_sortedD[b*NN + cnt] = di;
            }
        }
        grid_bar();

        // ============ PHASE 3: scanE (blk<4)  ||  scan_chunk (blk>=4) ========
        if (blk < BB) {
            int b = blk;
            const float* sd = g_sortedD + b*NN;
            float dm = __ldcg(&sd[NN-1]);
            int base = tid * 8;
            float4 v0 = __ldcg((const float4*)(sd + base));
            float4 v1 = __ldcg((const float4*)(sd + base + 4));
            float e[8];
            e[0]=expf(v0.x-dm); e[1]=expf(v0.y-dm); e[2]=expf(v0.z-dm); e[3]=expf(v0.w-dm);
            e[4]=expf(v1.x-dm); e[5]=expf(v1.y-dm); e[6]=expf(v1.z-dm); e[7]=expf(v1.w-dm);
            float ls[8];
            float tot = 0.f;
            #pragma unroll
            for (int j = 7; j >= 0; j--) { tot += e[j]; ls[j] = tot; }
            float* t0 = SM; float* t1 = SM + 256;
            t0[tid] = tot;
            __syncthreads();
            float* cur = t0; float* nxt = t1;
            #pragma unroll
            for (int off = 1; off < 256; off <<= 1) {
                float v = cur[tid];
                if (tid + off < 256) v += cur[tid + off];
                nxt[tid] = v;
                __syncthreads();
                float* tmp = cur; cur = nxt; nxt = tmp;
            }
            float tail = cur[tid] - tot;          // sum over threads > tid
            #pragma unroll
            for (int j = 0; j < 8; j++)
                g_sufE1[b*KTOT + base + j] = ls[j] + tail;
            if (tid == 0) g_sufE1[b*KTOT + NN] = 0.f;
        } else {
            int sub = tid >> 7, f = tid & 127;
            int*   rows = (int*)SM;               // [2][16]
            float* wv   = SM + 32;                // [2][16]
            for (int iter = 0; iter < 3; iter++) {
                int t = (blk - BB)*2 + sub + iter*248;
                int b = (t < 512) ? (t >> 7) : 0;
                int ch = t & 127;
                int k0 = ch * CLEN;
                if (t < 512 && f < 16) {
                    rows[sub*16 + f] = __ldcg(&g_perm[b*NN + k0 + f]);
                    float dm = __ldcg(&g_sortedD[b*NN + NN-1]);
                    wv[sub*16 + f] = expf(__ldcg(&g_sortedD[b*NN + k0 + f]) - dm);
                }
                __syncthreads();
                if (t < 512) {
                    const float* hb = g_h1 + b*NN*FD;
                    float v[16];
                    #pragma unroll
                    for (int j = 0; j < 16; j++)
                        v[j] = __ldcg(&hb[rows[sub*16+j]*FD + f]);
                    float acc = 0.f;
                    #pragma unroll
                    for (int j = 0; j < 16; j++) {
                        g_preH[(b*KTOT + k0 + j)*FD + f] = acc;
                        acc += v[j];
                    }
                    g_tot[((b*2+0)*NCH + ch)*FD + f] = acc;
                    acc = 0.f;
                    #pragma unroll
                    for (int j = 15; j >= 0; j--) {
                        acc += wv[sub*16+j] * v[j];
                        g_sufEH[(b*KTOT + k0 + j)*FD + f] = acc;
                    }
                    g_tot[((b*2+1)*NCH + ch)*FD + f] = acc;
                }
                __syncthreads();
            }
        }
        grid_bar();

        // ============ PHASE 4: chunk-offset scans (blk<4) + row scalars ======
        if (blk < BB) {
            int b = blk;
            int dir = tid >> 7, f = tid & 127;
            if (dir == 0) {
                float acc = 0.f;
                #pragma unroll 8
                for (int c = 0; c < NCH; c++) {
                    g_off[((b*2+0)*(NCH+1) + c)*FD + f] = acc;
                    acc += __ldcg(&g_tot[((b*2+0)*NCH + c)*FD + f]);
                }
                g_off[((b*2+0)*(NCH+1) + NCH)*FD + f] = acc;
                g_preH[(b*KTOT + NN)*FD + f] = 0.f;
            } else {
                float acc = 0.f;
                #pragma unroll 8
                for (int c = NCH-1; c >= 0; c--) {
                    g_off[((b*2+1)*(NCH+1) + c)*FD + f] = acc;
                    acc += __ldcg(&g_tot[((b*2+1)*NCH + c)*FD + f]);
                }
                g_off[((b*2+1)*(NCH+1) + NCH)*FD + f] = 0.f;
                g_sufEH[(b*KTOT + NN)*FD + f] = 0.f;
            }
        } else if (blk < BB + 32) {
            int row = (blk - BB)*256 + tid;
            int b = row >> 11;
            float c   = __ldcg(&g_s[row]) + abA[klay];
            float thr = -c;
            const float* sd = g_sortedD + b*NN;
            int lo = 0, hi = NN;
            while (lo < hi) { int mid = (lo+hi) >> 1; if (__ldcg(&sd[mid]) <= thr) lo = mid+1; else hi = mid; }
            int k = lo;
            float dm = __ldcg(&sd[NN-1]);
            float E  = expf(c + dm);
            float di = __ldcg(&g_d[row]);
            float w  = (di > thr) ? expf(c + di) : 1.0f;
            float den = E * __ldcg(&g_sufE1[b*KTOT + k]) + (float)k - w;
            g_rk[row]   = k;
            g_rE[row]   = E;
            g_rw[row]   = w;
            g_rinv[row] = 1.0f / den;
        }
        grid_bar();

        // ============ PHASE 5: combine (streaming) ===========================
        {
            int sub = tid >> 7, f = tid & 127;
            #pragma unroll 4
            for (int it = 0; it < 32; it++) {
                int row = blk*64 + it*2 + sub;
                int b = row >> 11;
                int i = row & (NN-1);
                int   k    = __ldcg(&g_rk[row]);
                float E    = __ldcg(&g_rE[row]);
                float wown = __ldcg(&g_rw[row]);
                float inv  = __ldcg(&g_rinv[row]);
                int ch = k >> 4;
                float pre = __ldcg(&g_preH [(b*KTOT + k)*FD + f])
                          + __ldcg(&g_off[((b*2+0)*(NCH+1) + ch)*FD + f]);
                float suf = __ldcg(&g_sufEH[(b*KTOT + k)*FD + f])
                          + __ldcg(&g_off[((b*2+1)*(NCH+1) + ch)*FD + f]);
                float h1v = __ldcg(&g_h1[row*FD + f]);
                float o = (E*suf + pre - wown*h1v) * inv;
                float h2v = __ldcg(&g_h2[row*FD + f]);
                if (stage == 0) {
                    float gv = fmaxf(o + h2v, 0.f);
                    float invs = rsqrtf(var[i] + 1e-5f);
                    gv = (gv - mean[i]) * (invs * gamma[i]) + beta[i];
                    g_g[row*FD + f] = gv;
                } else {
                    out[row*FD + f] = o + h2v;
                }
            }
        }
        if (stage == 0) grid_bar();
    }
}

// ---------------- orchestration: ONE launch ----------------
extern "C" void kernel_launch(void* const* d_in, const int* in_sizes, int n_in,
                              void* d_out, int out_size)
{
    (void)in_sizes; (void)n_in; (void)out_size;
    const float* x     = (const float*)d_in[0];
    const float* W1    = (const float*)d_in[2];
    const float* b1    = (const float*)d_in[3];
    const float* asrc  = (const float*)d_in[4];
    const float* adst  = (const float*)d_in[5];
    const float* ab    = (const float*)d_in[6];
    const float* gamma = (const float*)d_in[7];
    const float* beta  = (const float*)d_in[8];
    const float* mean  = (const float*)d_in[9];
    const float* var   = (const float*)d_in[10];
    float* out = (float*)d_out;

    gat_mega<<<NBLK, NTHR>>>(x, W1, b1, asrc, adst, ab,
                             gamma, beta, mean, var, out);
}

// round 16
// speedup vs baseline: 1.1745x; 1.1745x over previous
#include <cuda_runtime.h>
#include <math.h>

#define BB 4
#define NN 2048
#define FD 128
#define MROWS (BB*NN)     // 8192 rows
#define KTOT (NN+1)
#define NCH 128
#define CLEN 16
#define NBLKB 256         // mid-kernel persistent grid (2 CTAs/SM)

// ---------------- scratch (device globals; no allocation) ----------------
__device__ float g_h1[MROWS*FD];
__device__ float g_h2[MROWS*FD];
__device__ float g_g [MROWS*FD];
__device__ float g_s[MROWS];
__device__ float g_d[MROWS];
__device__ float g_sortedD[MROWS];
__device__ int   g_perm[MROWS];
__device__ float g_sufE1[BB*KTOT];
__device__ float g_preH [BB*KTOT*FD];
__device__ float g_sufEH[BB*KTOT*FD];
__device__ float g_tot[BB*2*NCH*FD];
__device__ float g_off[BB*2*(NCH+1)*FD];
__device__ int   g_rk[MROWS];
__device__ float g_rE[MROWS];
__device__ float g_rw[MROWS];
__device__ float g_rinv[MROWS];

// ---------------- software grid barrier (mid-kernel only) ----------------
__device__ unsigned g_bar_cnt = 0;
__device__ volatile unsigned g_bar_gen = 0;

__device__ __forceinline__ void grid_bar() {
    __threadfence();
    __syncthreads();
    if (threadIdx.x == 0) {
        unsigned gen = g_bar_gen;
        if (atomicAdd(&g_bar_cnt, 1u) == NBLKB - 1u) {
            g_bar_cnt = 0u;
            __threadfence();
            g_bar_gen = gen + 1u;
        } else {
            while (g_bar_gen == gen) __nanosleep(32);
        }
    }
    __syncthreads();
}

// ---------------- tf32 helpers ----------------
__device__ __forceinline__ float tf32_rn(float x) {
    unsigned u;
    asm("cvt.rna.tf32.f32 %0, %1;" : "=r"(u) : "f"(x));
    return __uint_as_float(u);
}

__device__ __forceinline__ void mma8(float* d, const float* a, float b0, float b1) {
    asm volatile(
        "mma.sync.aligned.m16n8k8.row.col.f32.tf32.tf32.f32 "
        "{%0,%1,%2,%3},{%4,%5,%6,%7},{%8,%9},{%0,%1,%2,%3};"
        : "+f"(d[0]), "+f"(d[1]), "+f"(d[2]), "+f"(d[3])
        : "r"(__float_as_uint(a[0])), "r"(__float_as_uint(a[1])),
          "r"(__float_as_uint(a[2])), "r"(__float_as_uint(a[3])),
          "r"(__float_as_uint(b0)),  "r"(__float_as_uint(b1)));
}

// ---------------- fused linear (3xTF32 mma) + fused s/d dot in epilogue -----
#define KC 16
__global__ __launch_bounds__(256) void gemm_tf32_kernel(
    const float* __restrict__ Xext, int useG,
    const float* __restrict__ W, const float* __restrict__ bias,
    const float* __restrict__ asrc, const float* __restrict__ adst)
{
    const float* __restrict__ X = useG ? g_g : Xext;
    __shared__ float Ah[128][KC+1], Al[128][KC+1];
    __shared__ float Bh[128][KC+1], Bl[128][KC+1];
    __shared__ float sh_s[2][128], sh_d[2][128];
    int tid = threadIdx.x;
    int wid = tid >> 5, lane = tid & 31;
    int gid = lane >> 2, tig = lane & 3;
    int warp_m = wid & 3;
    int warp_n = wid >> 2;
    int row0 = blockIdx.x * 128;
    int col0 = blockIdx.y * 128;

    float acc[2][8][4];
    #pragma unroll
    for (int mt = 0; mt < 2; mt++)
        #pragma unroll
        for (int nt = 0; nt < 8; nt++)
            #pragma unroll
            for (int q = 0; q < 4; q++) acc[mt][nt][q] = 0.f;

    int lrow = tid >> 2;          // 0..63
    int lq = (tid & 3) * 4;       // 0,4,8,12

    for (int kt = 0; kt < FD; kt += KC) {
        float4 xa = *(const float4*)(X + (row0+lrow   )*FD + kt + lq);
        float4 xb = *(const float4*)(X + (row0+lrow+64)*FD + kt + lq);
        float4 wa = *(const float4*)(W + (col0+lrow   )*FD + kt + lq);
        float4 wb = *(const float4*)(W + (col0+lrow+64)*FD + kt + lq);
        __syncthreads();
        {
            float v[4] = {xa.x, xa.y, xa.z, xa.w};
            #pragma unroll
            for (int c = 0; c < 4; c++) {
                float h = tf32_rn(v[c]);
                Ah[lrow][lq+c] = h; Al[lrow][lq+c] = tf32_rn(v[c] - h);
            }
        }
        {
            float v[4] = {xb.x, xb.y, xb.z, xb.w};
            #pragma unroll
            for (int c = 0; c < 4; c++) {
                float h = tf32_rn(v[c]);
                Ah[lrow+64][lq+c] = h; Al[lrow+64][lq+c] = tf32_rn(v[c] - h);
            }
        }
        {
            float v[4] = {wa.x, wa.y, wa.z, wa.w};
            #pragma unroll
            for (int c = 0; c < 4; c++) {
                float h = tf32_rn(v[c]);
                Bh[lrow][lq+c] = h; Bl[lrow][lq+c] = tf32_rn(v[c] - h);
            }
        }
        {
            float v[4] = {wb.x, wb.y, wb.z, wb.w};
            #pragma unroll
            for (int c = 0; c < 4; c++) {
                float h = tf32_rn(v[c]);
                Bh[lrow+64][lq+c] = h; Bl[lrow+64][lq+c] = tf32_rn(v[c] - h);
            }
        }
        __syncthreads();

        #pragma unroll
        for (int kk = 0; kk < KC; kk += 8) {
            float a_h[2][4], a_l[2][4];
            #pragma unroll
            for (int mt = 0; mt < 2; mt++) {
                int r = warp_m*32 + mt*16;
                a_h[mt][0] = Ah[r+gid  ][kk+tig];   a_h[mt][1] = Ah[r+gid+8][kk+tig];
                a_h[mt][2] = Ah[r+gid  ][kk+tig+4]; a_h[mt][3] = Ah[r+gid+8][kk+tig+4];
                a_l[mt][0] = Al[r+gid  ][kk+tig];   a_l[mt][1] = Al[r+gid+8][kk+tig];
                a_l[mt][2] = Al[r+gid  ][kk+tig+4]; a_l[mt][3] = Al[r+gid+8][kk+tig+4];
            }
            #pragma unroll
            for (int nt = 0; nt < 8; nt++) {
                int cc = warp_n*64 + nt*8 + gid;
                float bh0 = Bh[cc][kk+tig], bh1 = Bh[cc][kk+tig+4];
                float bl0 = Bl[cc][kk+tig], bl1 = Bl[cc][kk+tig+4];
                #pragma unroll
                for (int mt = 0; mt < 2; mt++) {
                    mma8(acc[mt][nt], a_h[mt], bh0, bh1);
                    mma8(acc[mt][nt], a_l[mt], bh0, bh1);
                    mma8(acc[mt][nt], a_h[mt], bl0, bl1);
                }
            }
        }
    }

    float* D = (blockIdx.y == 0) ? g_h1 : g_h2;
    float ps[2][2] = {{0.f,0.f},{0.f,0.f}};
    float pd[2][2] = {{0.f,0.f},{0.f,0.f}};
    #pragma unroll
    for (int mt = 0; mt < 2; mt++) {
        #pragma unroll
        for (int nt = 0; nt < 8; nt++) {
            int col = warp_n*64 + nt*8 + tig*2;
            float bv0 = bias[col0 + col];
            float bv1 = bias[col0 + col + 1];
            float v00 = acc[mt][nt][0]+bv0, v01 = acc[mt][nt][1]+bv1;
            float v10 = acc[mt][nt][2]+bv0, v11 = acc[mt][nt][3]+bv1;
            int r0 = row0 + warp_m*32 + mt*16 + gid;
            *(float2*)(D + r0*FD + col)     = make_float2(v00, v01);
            *(float2*)(D + (r0+8)*FD + col) = make_float2(v10, v11);
            if (blockIdx.y == 0) {
                float a0 = asrc[col], a1 = asrc[col+1];
                float d0 = adst[col], d1 = adst[col+1];
                ps[mt][0] += v00*a0 + v01*a1;  pd[mt][0] += v00*d0 + v01*d1;
                ps[mt][1] += v10*a0 + v11*a1;  pd[mt][1] += v10*d0 + v11*d1;
            }
        }
    }
    if (blockIdx.y == 0) {
        #pragma unroll
        for (int mt = 0; mt < 2; mt++)
            #pragma unroll
            for (int sel = 0; sel < 2; sel++) {
                float sv = ps[mt][sel], dv = pd[mt][sel];
                sv += __shfl_xor_sync(0xffffffffu, sv, 1);
                sv += __shfl_xor_sync(0xffffffffu, sv, 2);
                dv += __shfl_xor_sync(0xffffffffu, dv, 1);
                dv += __shfl_xor_sync(0xffffffffu, dv, 2);
                if (tig == 0) {
                    int lrw = warp_m*32 + mt*16 + sel*8 + gid;
                    sh_s[warp_n][lrw] = sv;
                    sh_d[warp_n][lrw] = dv;
                }
            }
        __syncthreads();
        if (tid < 128) {
            g_s[row0 + tid] = sh_s[0][tid] + sh_s[1][tid];
            g_d[row0 + tid] = sh_d[0][tid] + sh_d[1][tid];
        }
    }
}

// ============ persistent MID kernel: rank -> scanE||chunk -> off+rows -> combine
// 256 blocks x 256 threads, 2 CTAs/SM resident (low regs), 3 grid barriers.
template<int MODE>
__global__ __launch_bounds__(256, 2) void mid_kernel(
    const float* __restrict__ abp, int layer,
    const float* __restrict__ gamma, const float* __restrict__ beta,
    const float* __restrict__ mean,  const float* __restrict__ var,
    float* __restrict__ out)
{
    __shared__ __align__(16) float SMB[NN];   // 8 KB, reused per phase
    const int blk = blockIdx.x;
    const int tid = threadIdx.x;

    // ---------- PHASE 1: brute-force exact rank (64 blocks/batch, 32 rows/blk)
    {
        int b = blk >> 6;
        int chunk = blk & 63;
        for (int j = tid; j < NN; j += 256) SMB[j] = g_d[b*NN + j];
        __syncthreads();
        int i = chunk*32 + (tid >> 3);
        int q = tid & 7;                        // 8 threads/row, 256 cmp each
        float di = SMB[i];
        int cnt = 0;
        int base = q * 256;
        #pragma unroll 8
        for (int t = 0; t < 256; t++) {
            int j = base + ((t + q*13) & 255);
            float dj = SMB[j];
            cnt += (dj < di) || (dj == di && j < i);
        }
        cnt += __shfl_xor_sync(0xffffffffu, cnt, 1);
        cnt += __shfl_xor_sync(0xffffffffu, cnt, 2);
        cnt += __shfl_xor_sync(0xffffffffu, cnt, 4);
        if (q == 0) {
            g_perm[b*NN + cnt] = i;
            g_sortedD[b*NN + cnt] = di;
        }
    }
    grid_bar();

    // ---------- PHASE 2: scanE (blk<4)  ||  scan_chunk (blk>=4) --------------
    if (blk < BB) {
        int b = blk;
        const float* sd = g_sortedD + b*NN;
        float dm = __ldcg(&sd[NN-1]);
        int base = tid * 8;
        float4 v0 = __ldcg((const float4*)(sd + base));
        float4 v1 = __ldcg((const float4*)(sd + base + 4));
        float e[8];
        e[0]=expf(v0.x-dm); e[1]=expf(v0.y-dm); e[2]=expf(v0.z-dm); e[3]=expf(v0.w-dm);
        e[4]=expf(v1.x-dm); e[5]=expf(v1.y-dm); e[6]=expf(v1.z-dm); e[7]=expf(v1.w-dm);
        float ls[8];
        float tot = 0.f;
        #pragma unroll
        for (int j = 7; j >= 0; j--) { tot += e[j]; ls[j] = tot; }
        float* t0 = SMB; float* t1 = SMB + 256;
        t0[tid] = tot;
        __syncthreads();
        float* cur = t0; float* nxt = t1;
        #pragma unroll
        for (int off = 1; off < 256; off <<= 1) {
            float v = cur[tid];
            if (tid + off < 256) v += cur[tid + off];
            nxt[tid] = v;
            __syncthreads();
            float* tmp = cur; cur = nxt; nxt = tmp;
        }
        float tail = cur[tid] - tot;
        #pragma unroll
        for (int j = 0; j < 8; j++)
            g_sufE1[b*KTOT + base + j] = ls[j] + tail;
        if (tid == 0) g_sufE1[b*KTOT + NN] = 0.f;
    } else {
        int sub = tid >> 7, f = tid & 127;
        int*   rows = (int*)SMB;                 // [2][16]
        float* wv   = SMB + 32;                  // [2][16]
        // 512 tasks over blocks 4..255 (2 per block; blocks 4..7 take 2 rounds)
        for (int t = (blk - BB)*2 + sub; ; t += 504) {
            int active = (t < 512);
            int b = active ? (t >> 7) : 0;
            int ch = t & 127;
            int k0 = ch * CLEN;
            if (active && f < CLEN) {
                rows[sub*16 + f] = __ldcg(&g_perm[b*NN + k0 + f]);
                float dm = __ldcg(&g_sortedD[b*NN + NN-1]);
                wv[sub*16 + f] = expf(__ldcg(&g_sortedD[b*NN + k0 + f]) - dm);
            }
            __syncthreads();
            if (active) {
                const float* hb = g_h1 + b*NN*FD;
                float v[CLEN];
                #pragma unroll
                for (int j = 0; j < CLEN; j++)
                    v[j] = hb[rows[sub*16+j]*FD + f];
                float acc = 0.f;
                #pragma unroll
                for (int j = 0; j < CLEN; j++) {
                    g_preH[(b*KTOT + k0 + j)*FD + f] = acc;
                    acc += v[j];
                }
                g_tot[((b*2+0)*NCH + ch)*FD + f] = acc;
                acc = 0.f;
                #pragma unroll
                for (int j = CLEN-1; j >= 0; j--) {
                    acc += wv[sub*16+j] * v[j];
                    g_sufEH[(b*KTOT + k0 + j)*FD + f] = acc;
                }
                g_tot[((b*2+1)*NCH + ch)*FD + f] = acc;
            }
            __syncthreads();
            if ((blk - BB)*2 + 504 >= 512) break;   // uniform per block
            if (t + 504 >= 512 + ((blk - BB)*2 + sub) - ((blk-BB)*2+sub)) { }
            if (t + 504 >= 512) break;
        }
    }
    grid_bar();

    // ---------- PHASE 3: chunk-offset scans (blk<4) + row scalars ------------
    if (blk < BB) {
        int b = blk;
        int dir = tid >> 7, f = tid & 127;
        if (dir == 0) {
            float acc = 0.f;
            #pragma unroll 8
            for (int c = 0; c < NCH; c++) {
                g_off[((b*2+0)*(NCH+1) + c)*FD + f] = acc;
                acc += __ldcg(&g_tot[((b*2+0)*NCH + c)*FD + f]);
            }
            g_off[((b*2+0)*(NCH+1) + NCH)*FD + f] = acc;
            g_preH[(b*KTOT + NN)*FD + f] = 0.f;
        } else {
            float acc = 0.f;
            #pragma unroll 8
            for (int c = NCH-1; c >= 0; c--) {
                g_off[((b*2+1)*(NCH+1) + c)*FD + f] = acc;
                acc += __ldcg(&g_tot[((b*2+1)*NCH + c)*FD + f]);
            }
            g_off[((b*2+1)*(NCH+1) + NCH)*FD + f] = 0.f;
            g_sufEH[(b*KTOT + NN)*FD + f] = 0.f;
        }
    } else if (blk < BB + 32) {
        int row = (blk - BB)*256 + tid;
        int b = row >> 11;
        float c   = g_s[row] + abp[layer];
        float thr = -c;
        const float* sd = g_sortedD + b*NN;
        int lo = 0, hi = NN;
        while (lo < hi) { int mid = (lo+hi) >> 1; if (__ldcg(&sd[mid]) <= thr) lo = mid+1; else hi = mid; }
        int k = lo;
        float dm = __ldcg(&sd[NN-1]);
        float E  = expf(c + dm);
        float di = g_d[row];
        float w  = (di > thr) ? expf(c + di) : 1.0f;
        float den = E * __ldcg(&g_sufE1[b*KTOT + k]) + (float)k - w;
        g_rk[row]   = k;
        g_rE[row]   = E;
        g_rw[row]   = w;
        g_rinv[row] = 1.0f / den;
    }
    grid_bar();

    // ---------- PHASE 4: combine (streaming, 32 rows/block) ------------------
    {
        int sub = tid >> 7, f = tid & 127;
        #pragma unroll 4
        for (int it = 0; it < 16; it++) {
            int row = blk*32 + it*2 + sub;
            int b = row >> 11;
            int i = row & (NN-1);
            int   k    = __ldcg(&g_rk[row]);
            float E    = __ldcg(&g_rE[row]);
            float wown = __ldcg(&g_rw[row]);
            float inv  = __ldcg(&g_rinv[row]);
            int ch = k >> 4;
            float pre = __ldcg(&g_preH [(b*KTOT + k)*FD + f])
                      + __ldcg(&g_off[((b*2+0)*(NCH+1) + ch)*FD + f]);
            float suf = __ldcg(&g_sufEH[(b*KTOT + k)*FD + f])
                      + __ldcg(&g_off[((b*2+1)*(NCH+1) + ch)*FD + f]);
            float h1v = g_h1[row*FD + f];
            float o = (E*suf + pre - wown*h1v) * inv;
            float h2v = g_h2[row*FD + f];
            if (MODE == 0) {
                float gv = fmaxf(o + h2v, 0.f);
                float invs = rsqrtf(var[i] + 1e-5f);
                gv = (gv - mean[i]) * (invs * gamma[i]) + beta[i];
                g_g[row*FD + f] = gv;
            } else {
                out[row*FD + f] = o + h2v;
            }
        }
    }
}

// ---------------- orchestration: 4 launches ----------------
extern "C" void kernel_launch(void* const* d_in, const int* in_sizes, int n_in,
                              void* d_out, int out_size)
{
    (void)in_sizes; (void)n_in; (void)out_size;
    const float* x     = (const float*)d_in[0];
    const float* W1    = (const float*)d_in[2];
    const float* b1    = (const float*)d_in[3];
    const float* asrc  = (const float*)d_in[4];
    const float* adst  = (const float*)d_in[5];
    const float* ab    = (const float*)d_in[6];
    const float* gamma = (const float*)d_in[7];
    const float* beta  = (const float*)d_in[8];
    const float* mean  = (const float*)d_in[9];
    const float* var   = (const float*)d_in[10];
    float* out = (float*)d_out;

    for (int stage = 0; stage < 2; stage++) {
        int k = stage * 2;
        gemm_tf32_kernel<<<dim3(64, 2), 256>>>(x, stage, W1 + k*FD*FD, b1 + k*FD,
                                               asrc + k*FD, adst + k*FD);
        if (stage == 0)
            mid_kernel<0><<<NBLKB, 256>>>(ab, k, gamma, beta, mean, var, out);
        else
            mid_kernel<1><<<NBLKB, 256>>>(ab, k, gamma, beta, mean, var, out);
    }
}